// round 1
// baseline (speedup 1.0000x reference)
#include <cuda_runtime.h>
#include <cstdint>

// Fused 3-layer MLP, fp32 with packed f32x2 FMA (Blackwell FFMA2).
// One thread = one row. h1[128] register-resident (packed u64 pairs).
// W2 staged transposed in smem per 64-col chunk; W4 fully smem-resident.

#define TPB 256
#define ROWS_PER_BLOCK 256
#define W1_PAD 132   // 36 rows x 132 floats (16B-aligned rows)
#define W2T_PAD 136  // 64 rows x 136 floats (16B-aligned rows)

typedef unsigned long long ull;

__device__ __forceinline__ ull ffma2(ull a, ull b, ull c) {
    ull d;
    asm("fma.rn.f32x2 %0, %1, %2, %3;" : "=l"(d) : "l"(a), "l"(b), "l"(c));
    return d;
}
__device__ __forceinline__ ull pack2(float lo, float hi) {
    ull r;
    asm("mov.b64 %0, {%1, %2};" : "=l"(r) : "f"(lo), "f"(hi));
    return r;
}
__device__ __forceinline__ void unpack2(ull v, float& lo, float& hi) {
    asm("mov.b64 {%0, %1}, %2;" : "=f"(lo), "=f"(hi) : "l"(v));
}

// smem layout (floats):
//   xs   [3840]            rows of x for this block (256 x 15)
//   W1p  [36*132 = 4752]
//   b1s  [128]
//   b2s  [512]
//   W4s  [512*40 = 20480]
//   W2t  [64*136 = 8704]   current W2 chunk, transposed [j][k]
#define OFF_XS   0
#define OFF_W1   (OFF_XS + 3840)
#define OFF_B1   (OFF_W1 + 36 * W1_PAD)
#define OFF_B2   (OFF_B1 + 128)
#define OFF_W4   (OFF_B2 + 512)
#define OFF_W2T  (OFF_W4 + 512 * 40)
#define SMEM_FLOATS (OFF_W2T + 64 * W2T_PAD)

__global__ __launch_bounds__(TPB, 1)
void dqn_fused_kernel(const float* __restrict__ x,
                      const float* __restrict__ W1,
                      const float* __restrict__ b1,
                      const float* __restrict__ W2,
                      const float* __restrict__ b2,
                      const float* __restrict__ W4,
                      const float* __restrict__ b4,
                      float* __restrict__ out) {
    extern __shared__ float sm[];
    float* xs  = sm + OFF_XS;
    float* W1p = sm + OFF_W1;
    float* b1s = sm + OFF_B1;
    float* b2s = sm + OFF_B2;
    float* W4s = sm + OFF_W4;
    float* W2t = sm + OFF_W2T;

    const int t   = threadIdx.x;
    const int blk = blockIdx.x;

    // ---- stage x rows (coalesced) ----
    {
        const float* xblk = x + (size_t)blk * (ROWS_PER_BLOCK * 15);
        #pragma unroll
        for (int i = 0; i < 15; i++) xs[t + TPB * i] = xblk[t + TPB * i];
    }
    // ---- stage W1 (padded rows) ----
    for (int idx = t; idx < 36 * 128; idx += TPB)
        W1p[(idx >> 7) * W1_PAD + (idx & 127)] = W1[idx];
    if (t < 128) b1s[t] = b1[t];
    #pragma unroll
    for (int i = 0; i < 2; i++) b2s[t + TPB * i] = b2[t + TPB * i];
    // ---- stage W4 (same layout: [512][40]) ----
    #pragma unroll
    for (int i = 0; i < 80; i++) W4s[t + TPB * i] = W4[t + TPB * i];
    __syncthreads();

    // ---- per-row features ----
    const float* xr = xs + t * 15;
    float keep[11];
    #pragma unroll
    for (int k = 0; k < 11; k++) keep[k] = xr[k];
    int hidx = (int)xr[11];  hidx = hidx < 0 ? 0 : (hidx > 3 ? 3 : hidx);
    int n0 = (int)xr[12] - 1; n0 = n0 < 0 ? 0 : (n0 > 6 ? 6 : n0);
    int n1 = (int)xr[13] - 1; n1 = n1 < 0 ? 0 : (n1 > 6 ? 6 : n1);
    int n2 = (int)xr[14] - 1; n2 = n2 < 0 ? 0 : (n2 > 6 ? 6 : n2);

    const float* hrow = W1p + (11 + hidx) * W1_PAD;
    const float* r0   = W1p + (15 + n0)  * W1_PAD;
    const float* r1   = W1p + (22 + n1)  * W1_PAD;
    const float* r2   = W1p + (29 + n2)  * W1_PAD;

    // ---- layer 1: h1 = relu(inp @ W1 + b1), register-resident packed ----
    ull h1p[64];
    #pragma unroll
    for (int c4 = 0; c4 < 32; c4++) {
        const int c = c4 * 4;
        float4 acc = *(const float4*)(b1s + c);
        #pragma unroll
        for (int k = 0; k < 11; k++) {
            float4 w = *(const float4*)(W1p + k * W1_PAD + c);
            acc.x += keep[k] * w.x; acc.y += keep[k] * w.y;
            acc.z += keep[k] * w.z; acc.w += keep[k] * w.w;
        }
        float4 wh = *(const float4*)(hrow + c);
        float4 w0 = *(const float4*)(r0 + c);
        float4 w1 = *(const float4*)(r1 + c);
        float4 w2 = *(const float4*)(r2 + c);
        acc.x += wh.x + w0.x + w1.x + w2.x;
        acc.y += wh.y + w0.y + w1.y + w2.y;
        acc.z += wh.z + w0.z + w1.z + w2.z;
        acc.w += wh.w + w0.w + w1.w + w2.w;
        acc.x = fmaxf(acc.x, 0.f); acc.y = fmaxf(acc.y, 0.f);
        acc.z = fmaxf(acc.z, 0.f); acc.w = fmaxf(acc.w, 0.f);
        h1p[2 * c4]     = pack2(acc.x, acc.y);
        h1p[2 * c4 + 1] = pack2(acc.z, acc.w);
    }

    // ---- output accumulator (40 floats packed), init with b4 ----
    ull outp[20];
    #pragma unroll
    for (int i = 0; i < 20; i++)
        outp[i] = pack2(__ldg(b4 + 2 * i), __ldg(b4 + 2 * i + 1));

    // ---- layers 2+3 fused, 8 chunks of 64 h2-columns ----
    for (int c = 0; c < 8; c++) {
        __syncthreads();  // prior chunk fully consumed
        // fill W2t[j][k] = W2[k][c*64+j]  (coalesced global reads)
        #pragma unroll
        for (int i = 0; i < 32; i++) {
            int idx = i * TPB + t;
            int j = idx & 63;
            int k = idx >> 6;
            W2t[j * W2T_PAD + k] = W2[k * 512 + c * 64 + j];
        }
        __syncthreads();

        const int jg_base = c * 64;
        #pragma unroll 1
        for (int jj = 0; jj < 32; jj++) {
            const int j0 = 2 * jj;
            const float* p0 = W2t + j0 * W2T_PAD;
            const float* p1 = p0 + W2T_PAD;
            ull a00 = 0ull, a01 = 0ull, a10 = 0ull, a11 = 0ull;
            #pragma unroll
            for (int k4 = 0; k4 < 32; k4++) {
                ulonglong2 w0 = *(const ulonglong2*)(p0 + k4 * 4);
                ulonglong2 w1 = *(const ulonglong2*)(p1 + k4 * 4);
                a00 = ffma2(h1p[2 * k4],     w0.x, a00);
                a01 = ffma2(h1p[2 * k4 + 1], w0.y, a01);
                a10 = ffma2(h1p[2 * k4],     w1.x, a10);
                a11 = ffma2(h1p[2 * k4 + 1], w1.y, a11);
            }
            float l0, h0, l1, h1v;
            unpack2(a00, l0, h0); unpack2(a01, l1, h1v);
            float s0 = fmaxf(l0 + h0 + l1 + h1v + b2s[jg_base + j0], 0.f);
            unpack2(a10, l0, h0); unpack2(a11, l1, h1v);
            float s1 = fmaxf(l0 + h0 + l1 + h1v + b2s[jg_base + j0 + 1], 0.f);

            ull s0p = pack2(s0, s0);
            ull s1p = pack2(s1, s1);
            const float* q0 = W4s + (jg_base + j0) * 40;
            const float* q1 = q0 + 40;
            #pragma unroll
            for (int m4 = 0; m4 < 10; m4++) {
                ulonglong2 wa = *(const ulonglong2*)(q0 + m4 * 4);
                ulonglong2 wb = *(const ulonglong2*)(q1 + m4 * 4);
                ull v0 = ffma2(s0p, wa.x, outp[2 * m4]);
                outp[2 * m4] = ffma2(s1p, wb.x, v0);
                ull v1 = ffma2(s0p, wa.y, outp[2 * m4 + 1]);
                outp[2 * m4 + 1] = ffma2(s1p, wb.y, v1);
            }
        }
    }

    // ---- write out row ----
    float* orow = out + (size_t)(blk * ROWS_PER_BLOCK + t) * 40;
    #pragma unroll
    for (int i = 0; i < 10; i++) {
        float a, b, cc, d;
        unpack2(outp[2 * i], a, b);
        unpack2(outp[2 * i + 1], cc, d);
        float4 v = make_float4(a, b, cc, d);
        *(float4*)(orow + 4 * i) = v;
    }
}

extern "C" void kernel_launch(void* const* d_in, const int* in_sizes, int n_in,
                              void* d_out, int out_size) {
    const float* x  = (const float*)d_in[0];
    const float* W1 = (const float*)d_in[1];
    const float* b1 = (const float*)d_in[2];
    const float* W2 = (const float*)d_in[3];
    const float* b2 = (const float*)d_in[4];
    const float* W4 = (const float*)d_in[5];
    const float* b4 = (const float*)d_in[6];
    float* out = (float*)d_out;

    const int B = in_sizes[0] / 15;  // 131072
    const int grid = B / ROWS_PER_BLOCK;
    const size_t smem = SMEM_FLOATS * sizeof(float);

    cudaFuncSetAttribute(dqn_fused_kernel,
                         cudaFuncAttributeMaxDynamicSharedMemorySize, (int)smem);
    dqn_fused_kernel<<<grid, TPB, smem>>>(x, W1, b1, W2, b2, W4, b4, out);
}

// round 2
// speedup vs baseline: 1.5019x; 1.5019x over previous
#include <cuda_runtime.h>
#include <cstdint>

// Fused 3-layer MLP, fp32, packed f32x2 FMA, smem-tiled GEMM.
// Block = 128 rows. h1[128k][128r] in smem. W2 in 4 chunks of 128 cols.
// Layer2: per-thread 8x8 register tile (rows packed in f32x2 pairs).
// Layer3: fused per chunk via h2 chunk staged in the W2 buffer; per-thread
//         2 rows x 10 cols (cols packed in f32x2 pairs).

#define TPB 256
#define RPB 128
#define JPAD 136

typedef unsigned long long ull;

__device__ __forceinline__ ull ffma2(ull a, ull b, ull c) {
    ull d;
    asm("fma.rn.f32x2 %0, %1, %2, %3;" : "=l"(d) : "l"(a), "l"(b), "l"(c));
    return d;
}
__device__ __forceinline__ ull pack2(float lo, float hi) {
    ull r;
    asm("mov.b64 %0, {%1, %2};" : "=l"(r) : "f"(lo), "f"(hi));
    return r;
}
__device__ __forceinline__ void unpack2(ull v, float& lo, float& hi) {
    asm("mov.b64 {%0, %1}, %2;" : "=f"(lo), "=f"(hi) : "l"(v));
}

// smem layout (floats)
#define OFF_H1   0                    // 128*128 = 16384   h1s[k][row]
#define OFF_BUF  16384                // 17408: W2 chunk [k][j] / h2 chunk [r][j,JPAD] / layer1 staging
#define OFF_W4   (16384 + 17408)      // 128*40 = 5120     W4 chunk [j][m]
#define OFF_B2   (OFF_W4 + 5120)      // 512
#define SMEM_FLOATS (OFF_B2 + 512)    // 39424 floats = 157696 B

__global__ __launch_bounds__(TPB, 1)
void dqn_tiled_kernel(const float* __restrict__ x,
                      const float* __restrict__ W1,
                      const float* __restrict__ b1,
                      const float* __restrict__ W2,
                      const float* __restrict__ b2,
                      const float* __restrict__ W4,
                      const float* __restrict__ b4,
                      float* __restrict__ out) {
    extern __shared__ float sm[];
    float* h1s = sm + OFF_H1;
    float* buf = sm + OFF_BUF;
    float* w4s = sm + OFF_W4;
    float* b2s = sm + OFF_B2;

    const int t   = threadIdx.x;
    const int blk = blockIdx.x;

    // ---------------- layer 1 (staging aliased into buf) ----------------
    {
        float* xs  = buf;           // 128*15 = 1920
        float* W1p = buf + 1920;    // 36*128 = 4608
        float* b1s = buf + 6528;    // 128

        const float* xg = x + (size_t)blk * (RPB * 15);
        #pragma unroll
        for (int i = 0; i < 8; i++) {
            int idx = i * TPB + t;
            if (idx < 1920) xs[idx] = xg[idx];
        }
        #pragma unroll
        for (int i = 0; i < 18; i++) W1p[i * TPB + t] = W1[i * TPB + t];
        if (t < 128) b1s[t] = b1[t];
        #pragma unroll
        for (int i = 0; i < 2; i++) b2s[i * TPB + t] = b2[i * TPB + t];
        __syncthreads();

        const int r  = t & 127;
        const int ch = t >> 7;          // which 64-col half
        const float* xr = xs + r * 15;
        float keep[11];
        #pragma unroll
        for (int k = 0; k < 11; k++) keep[k] = xr[k];
        int hidx = (int)xr[11];  hidx = hidx < 0 ? 0 : (hidx > 3 ? 3 : hidx);
        int n0 = (int)xr[12] - 1; n0 = n0 < 0 ? 0 : (n0 > 6 ? 6 : n0);
        int n1 = (int)xr[13] - 1; n1 = n1 < 0 ? 0 : (n1 > 6 ? 6 : n1);
        int n2 = (int)xr[14] - 1; n2 = n2 < 0 ? 0 : (n2 > 6 ? 6 : n2);
        const float* hrow = W1p + (11 + hidx) * 128;
        const float* g0   = W1p + (15 + n0)  * 128;
        const float* g1   = W1p + (22 + n1)  * 128;
        const float* g2   = W1p + (29 + n2)  * 128;

        #pragma unroll
        for (int c4 = 0; c4 < 16; c4++) {
            const int c = ch * 64 + c4 * 4;
            float4 acc = *(const float4*)(b1s + c);
            #pragma unroll
            for (int k = 0; k < 11; k++) {
                float4 w = *(const float4*)(W1p + k * 128 + c);
                acc.x += keep[k] * w.x; acc.y += keep[k] * w.y;
                acc.z += keep[k] * w.z; acc.w += keep[k] * w.w;
            }
            float4 wh = *(const float4*)(hrow + c);
            float4 w0 = *(const float4*)(g0 + c);
            float4 w1 = *(const float4*)(g1 + c);
            float4 w2 = *(const float4*)(g2 + c);
            acc.x = fmaxf(acc.x + wh.x + w0.x + w1.x + w2.x, 0.f);
            acc.y = fmaxf(acc.y + wh.y + w0.y + w1.y + w2.y, 0.f);
            acc.z = fmaxf(acc.z + wh.z + w0.z + w1.z + w2.z, 0.f);
            acc.w = fmaxf(acc.w + wh.w + w0.w + w1.w + w2.w, 0.f);
            h1s[(c + 0) * 128 + r] = acc.x;
            h1s[(c + 1) * 128 + r] = acc.y;
            h1s[(c + 2) * 128 + r] = acc.z;
            h1s[(c + 3) * 128 + r] = acc.w;
        }
    }

    // ---------------- thread tile mappings ----------------
    const int tx  = t & 15;        // layer2 j-group
    const int ty  = t >> 4;        // layer2 row-group
    const int r0  = ty * 8;
    const int jl0 = tx * 8;

    const int rg  = t >> 2;        // layer3 row-pair group (0..63)
    const int gr0 = rg * 2;
    const int m0  = (t & 3) * 10;  // layer3 col base

    // layer3 output accumulators: [2 rows][5 col-pairs], packed along cols
    ull o3[10];
    #pragma unroll
    for (int mp = 0; mp < 5; mp++) {
        float2 bv = __ldg((const float2*)(b4 + m0 + mp * 2));
        ull v = pack2(bv.x, bv.y);
        o3[mp] = v; o3[5 + mp] = v;
    }

    // ---------------- chunk loop: layers 2+3 ----------------
    for (int c = 0; c < 4; c++) {
        __syncthreads();   // buf/w4s free from previous phase
        // stage W2 chunk [k][j] -> buf (first 16384 floats)
        #pragma unroll
        for (int i = 0; i < 64; i++) {
            int idx = i * TPB + t;
            int k = idx >> 7, j = idx & 127;
            buf[idx] = W2[k * 512 + c * 128 + j];
        }
        // stage W4 chunk [j][m]
        #pragma unroll
        for (int i = 0; i < 20; i++) {
            int idx = i * TPB + t;
            w4s[idx] = W4[c * 5120 + idx];
        }
        __syncthreads();

        // ---- layer2: 8x8 register tile, rows packed in pairs ----
        ull acc[32];
        #pragma unroll
        for (int i = 0; i < 32; i++) acc[i] = 0ull;
        {
            const float* hbase = h1s + r0;
            const float* wbase = buf + jl0;
            #pragma unroll 8
            for (int k = 0; k < 128; k++) {
                ulonglong2 a01 = *(const ulonglong2*)(hbase + k * 128);
                ulonglong2 a23 = *(const ulonglong2*)(hbase + k * 128 + 4);
                float4 wv0 = *(const float4*)(wbase + k * 128);
                float4 wv1 = *(const float4*)(wbase + k * 128 + 4);
                ull av[4] = {a01.x, a01.y, a23.x, a23.y};
                float wv[8] = {wv0.x, wv0.y, wv0.z, wv0.w,
                               wv1.x, wv1.y, wv1.z, wv1.w};
                #pragma unroll
                for (int j = 0; j < 8; j++) {
                    ull bd = pack2(wv[j], wv[j]);
                    #pragma unroll
                    for (int rp = 0; rp < 4; rp++)
                        acc[rp * 8 + j] = ffma2(av[rp], bd, acc[rp * 8 + j]);
                }
            }
        }
        __syncthreads();   // all reads of W2 chunk complete

        // ---- epilogue: +b2, relu, store h2 chunk row-major [r][j] ----
        #pragma unroll
        for (int rp = 0; rp < 4; rp++) {
            float lo[8], hi[8];
            #pragma unroll
            for (int j = 0; j < 8; j++) {
                float bj = b2s[c * 128 + jl0 + j];
                float l, h; unpack2(acc[rp * 8 + j], l, h);
                lo[j] = fmaxf(l + bj, 0.f);
                hi[j] = fmaxf(h + bj, 0.f);
            }
            float* row0 = buf + (r0 + 2 * rp)     * JPAD + jl0;
            float* row1 = buf + (r0 + 2 * rp + 1) * JPAD + jl0;
            *(float4*)(row0)     = make_float4(lo[0], lo[1], lo[2], lo[3]);
            *(float4*)(row0 + 4) = make_float4(lo[4], lo[5], lo[6], lo[7]);
            *(float4*)(row1)     = make_float4(hi[0], hi[1], hi[2], hi[3]);
            *(float4*)(row1 + 4) = make_float4(hi[4], hi[5], hi[6], hi[7]);
        }
        __syncthreads();   // h2 chunk visible

        // ---- layer3 partial: out += h2_chunk @ W4_chunk ----
        {
            const float* h2b = buf + gr0 * JPAD;
            #pragma unroll 4
            for (int j = 0; j < 128; j++) {
                float a0 = h2b[j];
                float a1 = h2b[JPAD + j];
                ull a0d = pack2(a0, a0);
                ull a1d = pack2(a1, a1);
                const float2* wrow = (const float2*)(w4s + j * 40 + m0);
                #pragma unroll
                for (int mp = 0; mp < 5; mp++) {
                    float2 w = wrow[mp];
                    ull wd = pack2(w.x, w.y);
                    o3[mp]     = ffma2(a0d, wd, o3[mp]);
                    o3[5 + mp] = ffma2(a1d, wd, o3[5 + mp]);
                }
            }
        }
    }

    // ---------------- write output ----------------
    float* ob = out + ((size_t)blk * RPB + gr0) * 40 + m0;
    #pragma unroll
    for (int i = 0; i < 2; i++)
        #pragma unroll
        for (int mp = 0; mp < 5; mp++) {
            float lo, hi; unpack2(o3[i * 5 + mp], lo, hi);
            *(float2*)(ob + i * 40 + mp * 2) = make_float2(lo, hi);
        }
}

extern "C" void kernel_launch(void* const* d_in, const int* in_sizes, int n_in,
                              void* d_out, int out_size) {
    const float* x  = (const float*)d_in[0];
    const float* W1 = (const float*)d_in[1];
    const float* b1 = (const float*)d_in[2];
    const float* W2 = (const float*)d_in[3];
    const float* b2 = (const float*)d_in[4];
    const float* W4 = (const float*)d_in[5];
    const float* b4 = (const float*)d_in[6];
    float* out = (float*)d_out;

    const int B = in_sizes[0] / 15;      // 131072
    const int grid = B / RPB;            // 1024
    const size_t smem = SMEM_FLOATS * sizeof(float);

    cudaFuncSetAttribute(dqn_tiled_kernel,
                         cudaFuncAttributeMaxDynamicSharedMemorySize, (int)smem);
    dqn_tiled_kernel<<<grid, TPB, smem>>>(x, W1, b1, W2, b2, W4, b4, out);
}

// round 4
// speedup vs baseline: 3.5947x; 2.3934x over previous
#include <cuda_runtime.h>
#include <cuda_fp16.h>
#include <cstdint>

#define TPB 256
#define PAD 136   // fp16 elements per smem row (272B: conflict-free ldmatrix)

// ---------------- pre-split fp16 weights in device globals ----------------
// W2: 4 chunks of [128 n][136 k] fp16 (transposed: entry = W2[k][c*128+n])
__device__ __align__(16) unsigned char gW2h[4 * 34816];
__device__ __align__(16) unsigned char gW2l[4 * 34816];
// W4: 4 chunks of [40 n][136 k] fp16 (entry = W4[c*128+k][n])
__device__ __align__(16) unsigned char gW4h[4 * 10880];
__device__ __align__(16) unsigned char gW4l[4 * 10880];

__device__ __forceinline__ void split2h(float v, __half& h, __half& l) {
    h = __float2half_rn(v);
    l = __float2half_rn(v - __half2float(h));
}

__global__ void prep_kernel(const float* __restrict__ W2,
                            const float* __restrict__ W4) {
    int idx = blockIdx.x * blockDim.x + threadIdx.x;
    if (idx < 65536) {                    // W2 split
        int c = idx >> 14, rem = idx & 16383;
        int n = rem >> 7, k = rem & 127;
        float v = W2[k * 512 + c * 128 + n];
        __half h, l; split2h(v, h, l);
        uint32_t off = (uint32_t)c * 34816u + (uint32_t)(n * PAD + k) * 2u;
        *(__half*)(gW2h + off) = h;
        *(__half*)(gW2l + off) = l;
    } else if (idx < 65536 + 20480) {     // W4 split
        int i = idx - 65536;
        int c = i / 5120, rem = i % 5120;
        int n = rem / 128, k = rem % 128;
        float v = W4[(c * 128 + k) * 40 + n];
        __half h, l; split2h(v, h, l);
        uint32_t off = (uint32_t)c * 10880u + (uint32_t)(n * PAD + k) * 2u;
        *(__half*)(gW4h + off) = h;
        *(__half*)(gW4l + off) = l;
    }
}

// ---------------- PTX helpers ----------------
__device__ __forceinline__ uint32_t smem_u32(const void* p) {
    uint32_t a;
    asm("{ .reg .u64 t; cvta.to.shared.u64 t, %1; cvt.u32.u64 %0, t; }"
        : "=r"(a) : "l"(p));
    return a;
}
__device__ __forceinline__ void ldsm_x4(uint32_t* r, uint32_t addr) {
    asm volatile("ldmatrix.sync.aligned.m8n8.x4.shared.b16 {%0,%1,%2,%3}, [%4];"
        : "=r"(r[0]), "=r"(r[1]), "=r"(r[2]), "=r"(r[3]) : "r"(addr));
}
__device__ __forceinline__ void ldsm_x2(uint32_t* r, uint32_t addr) {
    asm volatile("ldmatrix.sync.aligned.m8n8.x2.shared.b16 {%0,%1}, [%2];"
        : "=r"(r[0]), "=r"(r[1]) : "r"(addr));
}
__device__ __forceinline__ void mma16816(float* d, const uint32_t* a, const uint32_t* b) {
    asm volatile("mma.sync.aligned.m16n8k16.row.col.f32.f16.f16.f32 "
        "{%0,%1,%2,%3}, {%4,%5,%6,%7}, {%8,%9}, {%0,%1,%2,%3};"
        : "+f"(d[0]), "+f"(d[1]), "+f"(d[2]), "+f"(d[3])
        : "r"(a[0]), "r"(a[1]), "r"(a[2]), "r"(a[3]), "r"(b[0]), "r"(b[1]));
}

// ---------------- smem layout (bytes) ----------------
#define S_A2H  0                       // h1 hi  [128][PAD] f16 = 34816
#define S_A2L  34816                   // h1 lo
#define S_B    69632                   // W2 chunk hi / h2 (A3) hi / layer1 staging
#define S_BL   104448                  // W2 chunk lo / h2 lo
#define S_W4H  139264                  // W4 chunk hi [40][PAD] = 10880
#define S_W4L  150144
#define S_BIAS 161024                  // b1(128) b2(512) b4(40) f32 = 2720
#define SMEM_BYTES 163744

__global__ __launch_bounds__(TPB, 1)
void dqn_hmma_kernel(const float* __restrict__ x,
                     const float* __restrict__ W1,
                     const float* __restrict__ b1,
                     const float* __restrict__ b2,
                     const float* __restrict__ b4,
                     float* __restrict__ out) {
    extern __shared__ char smem[];
    const uint32_t sb = smem_u32(smem);
    const int t    = threadIdx.x;
    const int wid  = t >> 5;
    const int lane = t & 31;
    const int blk  = blockIdx.x;

    float* b1s = (float*)(smem + S_BIAS);
    float* b2s = b1s + 128;
    float* b4s = b2s + 512;

    // ---------------- stage biases + layer1 inputs (staging aliases S_B) ----
    {
        float* xs  = (float*)(smem + S_B);    // 128*15 = 1920 f32
        float* W1p = xs + 1920;               // 36*128 = 4608 f32
        const float* xg = x + (size_t)blk * (128 * 15);
        #pragma unroll
        for (int i = 0; i < 8; i++) {
            int idx = i * TPB + t;
            if (idx < 1920) xs[idx] = xg[idx];
        }
        #pragma unroll
        for (int i = 0; i < 18; i++) W1p[i * TPB + t] = W1[i * TPB + t];
        if (t < 128) b1s[t] = b1[t];
        b2s[t] = b2[t];
        b2s[t + 256] = b2[t + 256];
        if (t < 40) b4s[t] = b4[t];
        __syncthreads();

        // ---------------- layer 1 (fp32 exact) -> split-fp16 A2 tile --------
        const int r  = t & 127;
        const int ch = t >> 7;
        const float* xr = xs + r * 15;
        float keep[11];
        #pragma unroll
        for (int k = 0; k < 11; k++) keep[k] = xr[k];
        int hh = (int)xr[11];      hh = hh < 0 ? 0 : (hh > 3 ? 3 : hh);
        int n0 = (int)xr[12] - 1;  n0 = n0 < 0 ? 0 : (n0 > 6 ? 6 : n0);
        int n1 = (int)xr[13] - 1;  n1 = n1 < 0 ? 0 : (n1 > 6 ? 6 : n1);
        int n2 = (int)xr[14] - 1;  n2 = n2 < 0 ? 0 : (n2 > 6 ? 6 : n2);
        const float* hrow = W1p + (11 + hh) * 128;
        const float* g0   = W1p + (15 + n0) * 128;
        const float* g1   = W1p + (22 + n1) * 128;
        const float* g2   = W1p + (29 + n2) * 128;

        #pragma unroll
        for (int c4 = 0; c4 < 16; c4++) {
            const int c = ch * 64 + c4 * 4;
            float4 acc = *(const float4*)(b1s + c);
            #pragma unroll
            for (int k = 0; k < 11; k++) {
                float4 w = *(const float4*)(W1p + k * 128 + c);
                acc.x += keep[k] * w.x; acc.y += keep[k] * w.y;
                acc.z += keep[k] * w.z; acc.w += keep[k] * w.w;
            }
            float4 wh = *(const float4*)(hrow + c);
            float4 w0 = *(const float4*)(g0 + c);
            float4 w1 = *(const float4*)(g1 + c);
            float4 w2 = *(const float4*)(g2 + c);
            acc.x = fmaxf(acc.x + wh.x + w0.x + w1.x + w2.x, 0.f);
            acc.y = fmaxf(acc.y + wh.y + w0.y + w1.y + w2.y, 0.f);
            acc.z = fmaxf(acc.z + wh.z + w0.z + w1.z + w2.z, 0.f);
            acc.w = fmaxf(acc.w + wh.w + w0.w + w1.w + w2.w, 0.f);
            __half hx, lx, hy, ly, hz, lz, hw, lw;
            split2h(acc.x, hx, lx); split2h(acc.y, hy, ly);
            split2h(acc.z, hz, lz); split2h(acc.w, hw, lw);
            uint32_t off = (uint32_t)(r * PAD + c) * 2u;
            *(__half2*)(smem + S_A2H + off)     = __halves2half2(hx, hy);
            *(__half2*)(smem + S_A2H + off + 4) = __halves2half2(hz, hw);
            *(__half2*)(smem + S_A2L + off)     = __halves2half2(lx, ly);
            *(__half2*)(smem + S_A2L + off + 4) = __halves2half2(lz, lw);
        }
    }
    __syncthreads();

    // ---------------- fragment lane mappings ----------------
    const int lr = lane & 15;              // ldmatrix A row offset
    const int lc = (lane >> 4) << 3;       // ldmatrix A col offset
    const int br = lane & 7;               // ldmatrix B row offset
    const int bc = ((lane >> 3) & 1) << 3; // ldmatrix B col offset
    const int gid = lane >> 2;
    const int tig = lane & 3;

    const int mi = wid & 3;                // layer2 M32 block
    const int ni = wid >> 2;               // layer2 N64 block
    const int mi3 = wid & 3;               // layer3 M32 block
    const int kh3 = wid >> 2;              // layer3 K-half

    float o3[2][5][4];
    #pragma unroll
    for (int a = 0; a < 2; a++)
        #pragma unroll
        for (int b = 0; b < 5; b++)
            #pragma unroll
            for (int d = 0; d < 4; d++) o3[a][b][d] = 0.f;

    // ---------------- chunk loop ----------------
    for (int c = 0; c < 4; c++) {
        // copy W2 chunk (split) + W4 chunk (split)
        {
            const uint4* s1 = (const uint4*)(gW2h + (size_t)c * 34816);
            const uint4* s2 = (const uint4*)(gW2l + (size_t)c * 34816);
            uint4* d1 = (uint4*)(smem + S_B);
            uint4* d2 = (uint4*)(smem + S_BL);
            #pragma unroll
            for (int i = 0; i < 9; i++) {
                int idx = i * TPB + t;
                if (idx < 2176) { d1[idx] = s1[idx]; d2[idx] = s2[idx]; }
            }
            const uint4* s3 = (const uint4*)(gW4h + (size_t)c * 10880);
            const uint4* s4 = (const uint4*)(gW4l + (size_t)c * 10880);
            uint4* d3 = (uint4*)(smem + S_W4H);
            uint4* d4 = (uint4*)(smem + S_W4L);
            #pragma unroll
            for (int i = 0; i < 3; i++) {
                int idx = i * TPB + t;
                if (idx < 680) { d3[idx] = s3[idx]; d4[idx] = s4[idx]; }
            }
        }
        __syncthreads();

        // ---- layer2: warp 32x64 tile, K=128, 3-term split ----
        float acc[2][8][4];
        #pragma unroll
        for (int a = 0; a < 2; a++)
            #pragma unroll
            for (int b = 0; b < 8; b++)
                #pragma unroll
                for (int d = 0; d < 4; d++) acc[a][b][d] = 0.f;

        #pragma unroll
        for (int kt = 0; kt < 8; kt++) {
            const int k0 = kt * 16;
            uint32_t ah[2][4], al[2][4];
            #pragma unroll
            for (int mt = 0; mt < 2; mt++) {
                int row0 = mi * 32 + mt * 16;
                uint32_t off = (uint32_t)((row0 + lr) * PAD + k0 + lc) * 2u;
                ldsm_x4(ah[mt], sb + S_A2H + off);
                ldsm_x4(al[mt], sb + S_A2L + off);
            }
            uint32_t bh[8][2], bl[8][2];
            #pragma unroll
            for (int nt = 0; nt < 8; nt++) {
                int nrow = ni * 64 + nt * 8;
                uint32_t off = (uint32_t)((nrow + br) * PAD + k0 + bc) * 2u;
                ldsm_x2(bh[nt], sb + S_B + off);
                ldsm_x2(bl[nt], sb + S_BL + off);
            }
            #pragma unroll
            for (int mt = 0; mt < 2; mt++)
                #pragma unroll
                for (int nt = 0; nt < 8; nt++) {
                    mma16816(acc[mt][nt], ah[mt], bh[nt]);
                    mma16816(acc[mt][nt], ah[mt], bl[nt]);
                    mma16816(acc[mt][nt], al[mt], bh[nt]);
                }
        }
        __syncthreads();   // all warps done reading W2 chunk

        // ---- epilogue: +b2, relu, split-fp16 -> h2 tile (aliases W2 buf) ----
        #pragma unroll
        for (int mt = 0; mt < 2; mt++)
            #pragma unroll
            for (int nt = 0; nt < 8; nt++) {
                int j = ni * 64 + nt * 8 + 2 * tig;
                float bj0 = b2s[c * 128 + j], bj1 = b2s[c * 128 + j + 1];
                int row0 = mi * 32 + mt * 16 + gid;
                int row1 = row0 + 8;
                float v0 = fmaxf(acc[mt][nt][0] + bj0, 0.f);
                float v1 = fmaxf(acc[mt][nt][1] + bj1, 0.f);
                float v2 = fmaxf(acc[mt][nt][2] + bj0, 0.f);
                float v3 = fmaxf(acc[mt][nt][3] + bj1, 0.f);
                __half h0, l0, h1, l1, h2v, l2, h3, l3;
                split2h(v0, h0, l0); split2h(v1, h1, l1);
                split2h(v2, h2v, l2); split2h(v3, h3, l3);
                uint32_t o0 = (uint32_t)(row0 * PAD + j) * 2u;
                uint32_t o1 = (uint32_t)(row1 * PAD + j) * 2u;
                *(__half2*)(smem + S_B  + o0) = __halves2half2(h0, h1);
                *(__half2*)(smem + S_BL + o0) = __halves2half2(l0, l1);
                *(__half2*)(smem + S_B  + o1) = __halves2half2(h2v, h3);
                *(__half2*)(smem + S_BL + o1) = __halves2half2(l2, l3);
            }
        __syncthreads();

        // ---- layer3 partial: h2 chunk x W4 chunk, K split across warp halves
        #pragma unroll
        for (int kt = 0; kt < 4; kt++) {
            const int k0 = kh3 * 64 + kt * 16;
            uint32_t ah[2][4], al[2][4];
            #pragma unroll
            for (int mt = 0; mt < 2; mt++) {
                int row0 = mi3 * 32 + mt * 16;
                uint32_t off = (uint32_t)((row0 + lr) * PAD + k0 + lc) * 2u;
                ldsm_x4(ah[mt], sb + S_B + off);
                ldsm_x4(al[mt], sb + S_BL + off);
            }
            uint32_t bh[5][2], bl[5][2];
            #pragma unroll
            for (int nt = 0; nt < 5; nt++) {
                uint32_t off = (uint32_t)((nt * 8 + br) * PAD + k0 + bc) * 2u;
                ldsm_x2(bh[nt], sb + S_W4H + off);
                ldsm_x2(bl[nt], sb + S_W4L + off);
            }
            #pragma unroll
            for (int mt = 0; mt < 2; mt++)
                #pragma unroll
                for (int nt = 0; nt < 5; nt++) {
                    mma16816(o3[mt][nt], ah[mt], bh[nt]);
                    mma16816(o3[mt][nt], ah[mt], bl[nt]);
                    mma16816(o3[mt][nt], al[mt], bh[nt]);
                }
        }
        __syncthreads();   // h2/W4 reads done before next chunk copy
    }

    // ---------------- cross-warp K reduction + output ----------------
    float* sred = (float*)smem;   // reuse A2 region: 128*40 f32 = 20480B
    if (kh3 == 1) {
        #pragma unroll
        for (int mt = 0; mt < 2; mt++)
            #pragma unroll
            for (int nt = 0; nt < 5; nt++) {
                int j = nt * 8 + 2 * tig;
                int r0 = mi3 * 32 + mt * 16 + gid;
                int r1 = r0 + 8;
                sred[r0 * 40 + j]     = o3[mt][nt][0];
                sred[r0 * 40 + j + 1] = o3[mt][nt][1];
                sred[r1 * 40 + j]     = o3[mt][nt][2];
                sred[r1 * 40 + j + 1] = o3[mt][nt][3];
            }
    }
    __syncthreads();
    if (kh3 == 0) {
        #pragma unroll
        for (int mt = 0; mt < 2; mt++)
            #pragma unroll
            for (int nt = 0; nt < 5; nt++) {
                int j = nt * 8 + 2 * tig;
                int r0 = mi3 * 32 + mt * 16 + gid;
                int r1 = r0 + 8;
                float s0 = o3[mt][nt][0] + sred[r0 * 40 + j]     + b4s[j];
                float s1 = o3[mt][nt][1] + sred[r0 * 40 + j + 1] + b4s[j + 1];
                float s2 = o3[mt][nt][2] + sred[r1 * 40 + j]     + b4s[j];
                float s3 = o3[mt][nt][3] + sred[r1 * 40 + j + 1] + b4s[j + 1];
                *(float2*)(out + ((size_t)blk * 128 + r0) * 40 + j) = make_float2(s0, s1);
                *(float2*)(out + ((size_t)blk * 128 + r1) * 40 + j) = make_float2(s2, s3);
            }
    }
}

extern "C" void kernel_launch(void* const* d_in, const int* in_sizes, int n_in,
                              void* d_out, int out_size) {
    const float* x  = (const float*)d_in[0];
    const float* W1 = (const float*)d_in[1];
    const float* b1 = (const float*)d_in[2];
    const float* W2 = (const float*)d_in[3];
    const float* b2 = (const float*)d_in[4];
    const float* W4 = (const float*)d_in[5];
    const float* b4 = (const float*)d_in[6];
    float* out = (float*)d_out;

    prep_kernel<<<336, 256>>>(W2, W4);

    const int B = in_sizes[0] / 15;      // 131072
    const int grid = B / 128;            // 1024
    cudaFuncSetAttribute(dqn_hmma_kernel,
                         cudaFuncAttributeMaxDynamicSharedMemorySize, SMEM_BYTES);
    dqn_hmma_kernel<<<grid, TPB, SMEM_BYTES>>>(x, W1, b1, b2, b4, out);
}